// round 7
// baseline (speedup 1.0000x reference)
#include <cuda_runtime.h>
#include <cuda_bf16.h>
#include <cstdint>

#define BATCH 2048
#define SEQ   128
#define FEAT  64
#define HID   512
#define NGATE 2048          // 4*HID, gate-interleaved: n = 4*j + g
#define TM    128
#define TN    128
#define TK    32
#define NTH   256
#define NCTA  128           // <= 148 SMs: residency (and thus barrier liveness) guaranteed

// smem stage layout (pitch-80B rows: 64B data + 16B pad, conflict-free ldmatrix)
#define PB       80
#define A_HI     0
#define A_MID    10240
#define B_HI     20480
#define B_MID    30720
#define STAGE    40960
#define BIAS_OFF 81920      // four 128-float bias tiles (L1a, L1b, L2a, L2b)
#define SMEM_DYN (BIAS_OFF + 2048)

// ---------------- static device buffers ----------------
__device__ __nv_bfloat16 g_U1h[NGATE * HID],  g_U1m[NGATE * HID];
__device__ __nv_bfloat16 g_W1h[NGATE * FEAT], g_W1m[NGATE * FEAT];
__device__ __nv_bfloat16 g_U2h[NGATE * HID],  g_U2m[NGATE * HID];
__device__ __nv_bfloat16 g_W2h[NGATE * HID],  g_W2m[NGATE * HID];
__device__ __nv_bfloat16 g_xh[(size_t)BATCH * SEQ * FEAT], g_xm[(size_t)BATCH * SEQ * FEAT];
__device__ __nv_bfloat16 g_h1h[2][BATCH * HID], g_h1m[2][BATCH * HID];
__device__ __nv_bfloat16 g_h2h[2][BATCH * HID], g_h2m[2][BATCH * HID];
__device__ float g_c1[BATCH * HID], g_c2[BATCH * HID];
__device__ float g_b1i[NGATE], g_b2i[NGATE];
__device__ unsigned g_bar_count = 0;
__device__ unsigned g_bar_gen = 0;

// ---------------- PTX helpers ----------------
__device__ __forceinline__ uint32_t smem_u32(const void* p) {
    uint32_t a;
    asm("{ .reg .u64 t; cvta.to.shared.u64 t, %1; cvt.u32.u64 %0, t; }" : "=r"(a) : "l"(p));
    return a;
}
__device__ __forceinline__ void cpa(uint32_t dst, const void* src) {
    asm volatile("cp.async.cg.shared.global [%0], [%1], 16;" :: "r"(dst), "l"(src));
}
__device__ __forceinline__ void cp_commit() { asm volatile("cp.async.commit_group;"); }
template <int N> __device__ __forceinline__ void cp_wait() {
    asm volatile("cp.async.wait_group %0;" :: "n"(N));
}
__device__ __forceinline__ void ldm4(uint32_t* r, uint32_t addr) {
    asm volatile("ldmatrix.sync.aligned.m8n8.x4.shared.b16 {%0,%1,%2,%3}, [%4];"
        : "=r"(r[0]), "=r"(r[1]), "=r"(r[2]), "=r"(r[3]) : "r"(addr));
}
__device__ __forceinline__ void mma16816(float* c, const uint32_t* a, const uint32_t* b) {
    asm volatile("mma.sync.aligned.m16n8k16.row.col.f32.bf16.bf16.f32 "
        "{%0,%1,%2,%3}, {%4,%5,%6,%7}, {%8,%9}, {%0,%1,%2,%3};"
        : "+f"(c[0]), "+f"(c[1]), "+f"(c[2]), "+f"(c[3])
        : "r"(a[0]), "r"(a[1]), "r"(a[2]), "r"(a[3]), "r"(b[0]), "r"(b[1]));
}
__device__ __forceinline__ float sigmoid_(float v) { return 1.0f / (1.0f + __expf(-v)); }

// grid-wide sense-reversing barrier (128 CTAs: residency guaranteed at occ>=1)
__device__ __forceinline__ void grid_barrier() {
    __syncthreads();
    if (threadIdx.x == 0) {
        unsigned my = *(volatile unsigned*)&g_bar_gen;   // sample BEFORE arrive
        __threadfence();
        unsigned prev = atomicAdd(&g_bar_count, 1u);
        if (prev == NCTA - 1) {
            atomicExch(&g_bar_count, 0u);
            __threadfence();
            atomicAdd(&g_bar_gen, 1u);                   // release
        } else {
            while (*(volatile unsigned*)&g_bar_gen == my) __nanosleep(40);
        }
        __threadfence();
    }
    __syncthreads();
}

// ---------------- one fused LSTM tile-step (R4-proven mainloop + epilogue) ----------------
__device__ __forceinline__ void tile_step(
    uint32_t sm_base, int m0, int n0, int wm, int wn, int lane, int tid,
    const __nv_bfloat16* __restrict__ hph, const __nv_bfloat16* __restrict__ hpm,
    const __nv_bfloat16* __restrict__ Uh,  const __nv_bfloat16* __restrict__ Um, int nRec,
    const __nv_bfloat16* __restrict__ xh,  const __nv_bfloat16* __restrict__ xm, int ldxA,
    const __nv_bfloat16* __restrict__ Wh,  const __nv_bfloat16* __restrict__ Wm, int ldBin, int nIn,
    const float* __restrict__ biasS, float* __restrict__ cst,
    __nv_bfloat16* __restrict__ hoh, __nv_bfloat16* __restrict__ hom, int first)
{
    __syncthreads();   // guard smem stage reuse across consecutive tile_steps

    const int rA  = (lane & 7) + ((lane >> 3) & 1) * 8;
    const int kbA = (lane >> 4) * 8;
    const int rB  = (lane & 7) + ((lane >> 4) & 1) * 8;
    const int kbB = ((lane >> 3) & 1) * 8;
    const uint32_t aoff = A_HI + (uint32_t)(wm * 64 + rA) * PB + kbA * 2;
    const uint32_t boff = B_HI + (uint32_t)(wn * 32 + rB) * PB + kbB * 2;

    float acc[4][4][4];
    #pragma unroll
    for (int a = 0; a < 4; ++a)
        #pragma unroll
        for (int b = 0; b < 4; ++b)
            #pragma unroll
            for (int c = 0; c < 4; ++c) acc[a][b][c] = 0.0f;

    const int nb = nRec + nIn;

    auto stage_load = [&](int it, int s) {
        const __nv_bfloat16 *Ah, *Am, *Bh, *Bm; int lda, ldb, k0;
        if (it < nRec) { Ah = hph; Am = hpm; lda = HID;  Bh = Uh; Bm = Um; ldb = HID;   k0 = it * TK; }
        else           { Ah = xh;  Am = xm;  lda = ldxA; Bh = Wh; Bm = Wm; ldb = ldBin; k0 = (it - nRec) * TK; }
        const uint32_t sb = sm_base + (uint32_t)s * STAGE;
        #pragma unroll
        for (int i = 0; i < 2; ++i) {
            int e = tid + i * NTH;
            int row = e >> 2, c = e & 3;
            uint32_t d = (uint32_t)row * PB + c * 16;
            size_t offa = (size_t)(m0 + row) * lda + k0 + c * 8;
            cpa(sb + A_HI  + d, Ah + offa);
            cpa(sb + A_MID + d, Am + offa);
            size_t offb = (size_t)(n0 + row) * ldb + k0 + c * 8;
            cpa(sb + B_HI  + d, Bh + offb);
            cpa(sb + B_MID + d, Bm + offb);
        }
    };

    stage_load(0, 0);
    cp_commit();

    for (int it = 0; it < nb; ++it) {
        if (it + 1 < nb) {
            stage_load(it + 1, (it + 1) & 1);
            cp_commit();
            cp_wait<1>();
        } else {
            cp_wait<0>();
        }
        __syncthreads();

        const uint32_t sb = sm_base + (uint32_t)(it & 1) * STAGE;
        #pragma unroll
        for (int ks = 0; ks < 2; ++ks) {
            uint32_t bh[2][4], bm[2][4];
            #pragma unroll
            for (int p = 0; p < 2; ++p) {
                uint32_t ba = sb + boff + (uint32_t)p * (16 * PB) + ks * 32;
                ldm4(bh[p], ba);
                ldm4(bm[p], ba + (B_MID - B_HI));
            }
            #pragma unroll
            for (int mi = 0; mi < 4; ++mi) {
                uint32_t ah[4], am[4];
                uint32_t aa = sb + aoff + (uint32_t)mi * (16 * PB) + ks * 32;
                ldm4(ah, aa);
                ldm4(am, aa + (A_MID - A_HI));
                #pragma unroll
                for (int ni = 0; ni < 4; ++ni) {
                    const uint32_t* bhp = &bh[ni >> 1][(ni & 1) * 2];
                    const uint32_t* bmp = &bm[ni >> 1][(ni & 1) * 2];
                    mma16816(acc[mi][ni], ah, bhp);
                    mma16816(acc[mi][ni], am, bhp);
                    mma16816(acc[mi][ni], ah, bmp);
                }
            }
        }
        __syncthreads();
    }

    // epilogue: bias + gate exchange + fused cell
    const int jbase = (n0 >> 2) + wn * 8;
    #pragma unroll
    for (int mi = 0; mi < 4; ++mi) {
        #pragma unroll
        for (int ni = 0; ni < 4; ++ni) {
            const int nl = wn * 32 + ni * 8 + (lane & 3) * 2;
            const float bb0 = biasS[nl], bb1 = biasS[nl + 1];
            #pragma unroll
            for (int r = 0; r < 2; ++r) {
                float v0 = acc[mi][ni][r * 2 + 0] + bb0;
                float v1 = acc[mi][ni][r * 2 + 1] + bb1;
                float o0 = __shfl_xor_sync(0xffffffffu, v0, 1);
                float o1 = __shfl_xor_sync(0xffffffffu, v1, 1);
                if ((lane & 1) == 0) {
                    const int m = m0 + wm * 64 + mi * 16 + (lane >> 2) + r * 8;
                    const int j = jbase + ni * 2 + ((lane & 3) >> 1);
                    const size_t idx = (size_t)m * HID + j;
                    float cp = first ? 0.0f : cst[idx];
                    float iv = sigmoid_(v0), fv = sigmoid_(v1);
                    float ci = fmaxf(o0, 0.0f), ov = sigmoid_(o1);
                    float cn = fv * cp + iv * ci;
                    cst[idx] = cn;
                    float hv = ov * fmaxf(cn, 0.0f);
                    __nv_bfloat16 hh = __float2bfloat16(hv);
                    hoh[idx] = hh;
                    hom[idx] = __float2bfloat16(hv - __bfloat162float(hv - 0.0f) == 0.0f ? hv - __bfloat162float(hh) : hv - __bfloat162float(hh));
                }
            }
        }
    }
}

// ---------------- persistent kernel: all 128 steps, both layers, dense head ----------------
__global__ __launch_bounds__(NTH, 1) void lstm_persistent(
    const __nv_bfloat16* __restrict__ xh, const __nv_bfloat16* __restrict__ xm,
    const float* __restrict__ Wd, const float* __restrict__ bd, float* __restrict__ out)
{
    extern __shared__ char smem[];
    const uint32_t sm_base = smem_u32(smem);
    float* biasS = reinterpret_cast<float*>(smem + BIAS_OFF);   // [4][128]: L1a,L1b,L2a,L2b

    const int tid  = threadIdx.x;
    const int wid  = tid >> 5;
    const int lane = tid & 31;
    const int wm   = wid >> 2;
    const int wn   = wid & 3;
    const int bid  = blockIdx.x;
    const int m0   = (bid & 15) * TM;
    const int n0a  = (bid >> 4) * TN;           // 0..7 * 128
    const int n0b  = n0a + (NGATE / 2);         // + 1024

    if (tid < TN) {
        biasS[0 * TN + tid] = g_b1i[n0a + tid];
        biasS[1 * TN + tid] = g_b1i[n0b + tid];
        biasS[2 * TN + tid] = g_b2i[n0a + tid];
        biasS[3 * TN + tid] = g_b2i[n0b + tid];
    }
    __syncthreads();

    __nv_bfloat16* h1h[2] = {g_h1h[0], g_h1h[1]};
    __nv_bfloat16* h1m[2] = {g_h1m[0], g_h1m[1]};
    __nv_bfloat16* h2h[2] = {g_h2h[0], g_h2h[1]};
    __nv_bfloat16* h2m[2] = {g_h2m[0], g_h2m[1]};

    // phase p: L1(t=p) and L2(t=p-1); both depend only on pre-barrier data
    for (int p = 0; p <= SEQ; ++p) {
        if (p < SEQ) {
            const int t = p, cu = t & 1, pv = (t - 1) & 1;
            const __nv_bfloat16* hh = t ? h1h[pv] : nullptr;
            const __nv_bfloat16* hm = t ? h1m[pv] : nullptr;
            const int nr = t ? (HID / TK) : 0;
            tile_step(sm_base, m0, n0a, wm, wn, lane, tid, hh, hm,
                      g_U1h, g_U1m, nr,
                      xh + (size_t)t * FEAT, xm + (size_t)t * FEAT, SEQ * FEAT,
                      g_W1h, g_W1m, FEAT, FEAT / TK,
                      biasS + 0 * TN, g_c1, h1h[cu], h1m[cu], t == 0);
            tile_step(sm_base, m0, n0b, wm, wn, lane, tid, hh, hm,
                      g_U1h, g_U1m, nr,
                      xh + (size_t)t * FEAT, xm + (size_t)t * FEAT, SEQ * FEAT,
                      g_W1h, g_W1m, FEAT, FEAT / TK,
                      biasS + 1 * TN, g_c1, h1h[cu], h1m[cu], t == 0);
        }
        if (p >= 1) {
            const int t = p - 1, cu = t & 1, pv = (t - 1) & 1;
            const __nv_bfloat16* hh = t ? h2h[pv] : nullptr;
            const __nv_bfloat16* hm = t ? h2m[pv] : nullptr;
            const int nr = t ? (HID / TK) : 0;
            tile_step(sm_base, m0, n0a, wm, wn, lane, tid, hh, hm,
                      g_U2h, g_U2m, nr,
                      h1h[cu], h1m[cu], HID,
                      g_W2h, g_W2m, HID, HID / TK,
                      biasS + 2 * TN, g_c2, h2h[cu], h2m[cu], t == 0);
            tile_step(sm_base, m0, n0b, wm, wn, lane, tid, hh, hm,
                      g_U2h, g_U2m, nr,
                      h1h[cu], h1m[cu], HID,
                      g_W2h, g_W2m, HID, HID / TK,
                      biasS + 3 * TN, g_c2, h2h[cu], h2m[cu], t == 0);
        }
        grid_barrier();
    }

    // dense head: 128 CTAs x 8 warps x 2 rows = 2048 batch rows
    {
        const int fin = (SEQ - 1) & 1;
        #pragma unroll
        for (int r = 0; r < 2; ++r) {
            const int b = (bid * 8 + wid) * 2 + r;
            const __nv_bfloat16* rh = h2h[fin] + (size_t)b * HID;
            const __nv_bfloat16* rm = h2m[fin] + (size_t)b * HID;
            float s = 0.0f;
            #pragma unroll
            for (int k = lane; k < HID; k += 32)
                s += (__bfloat162float(rh[k]) + __bfloat162float(rm[k])) * Wd[k];
            #pragma unroll
            for (int o = 16; o > 0; o >>= 1) s += __shfl_xor_sync(0xffffffffu, s, o);
            if (lane == 0) out[b] = s + bd[0];
        }
    }
}

// ---------------- prep kernels ----------------
__global__ void prep_weights_all(const float* __restrict__ U1, const float* __restrict__ W1,
                                 const float* __restrict__ U2, const float* __restrict__ W2)
{
    const int NU = NGATE * HID, NW = NGATE * FEAT;
    int idx = blockIdx.x * blockDim.x + threadIdx.x;
    const float* src; __nv_bfloat16 *dh, *dm; int K, li;
    if (idx < NU)               { src = U1; dh = g_U1h; dm = g_U1m; K = HID;  li = idx; }
    else if (idx < NU + NW)     { src = W1; dh = g_W1h; dm = g_W1m; K = FEAT; li = idx - NU; }
    else if (idx < 2 * NU + NW) { src = U2; dh = g_U2h; dm = g_U2m; K = HID;  li = idx - NU - NW; }
    else if (idx < 3 * NU + NW) { src = W2; dh = g_W2h; dm = g_W2m; K = HID;  li = idx - 2 * NU - NW; }
    else return;
    int n = li / K, k = li - n * K;
    int col = (n & 3) * HID + (n >> 2);          // gate-interleave: n = 4j+g
    float v = src[(size_t)k * NGATE + col];
    __nv_bfloat16 h = __float2bfloat16(v);
    dh[li] = h;
    dm[li] = __float2bfloat16(v - __bfloat162float(h));
}

__global__ void prep_bias(const float* __restrict__ b1, const float* __restrict__ b2)
{
    int n = blockIdx.x * blockDim.x + threadIdx.x;
    if (n >= NGATE) return;
    int col = (n & 3) * HID + (n >> 2);
    g_b1i[n] = b1[col];
    g_b2i[n] = b2[col];
}

__global__ void prep_x(const float* __restrict__ x, int n)
{
    int i = blockIdx.x * blockDim.x + threadIdx.x;
    if (i >= n) return;
    float v = x[i];
    __nv_bfloat16 h = __float2bfloat16(v);
    g_xh[i] = h;
    g_xm[i] = __float2bfloat16(v - __bfloat162float(h));
}

extern "C" void kernel_launch(void* const* d_in, const int* in_sizes, int n_in,
                              void* d_out, int out_size)
{
    const float* x  = (const float*)d_in[0];
    const float* W1 = (const float*)d_in[1];
    const float* U1 = (const float*)d_in[2];
    const float* b1 = (const float*)d_in[3];
    const float* W2 = (const float*)d_in[4];
    const float* U2 = (const float*)d_in[5];
    const float* b2 = (const float*)d_in[6];
    const float* Wd = (const float*)d_in[7];
    const float* bd = (const float*)d_in[8];
    float* out = (float*)d_out;

    cudaFuncSetAttribute(lstm_persistent, cudaFuncAttributeMaxDynamicSharedMemorySize, SMEM_DYN);

    __nv_bfloat16* xh; __nv_bfloat16* xm;
    cudaGetSymbolAddress((void**)&xh, g_xh);
    cudaGetSymbolAddress((void**)&xm, g_xm);

    {
        int ntot = 3 * NGATE * HID + NGATE * FEAT;
        prep_weights_all<<<(ntot + 255) / 256, 256>>>(U1, W1, U2, W2);
        prep_bias<<<(NGATE + 255) / 256, 256>>>(b1, b2);
        int nx = BATCH * SEQ * FEAT;
        prep_x<<<(nx + 255) / 256, 256>>>(x, nx);
    }

    lstm_persistent<<<NCTA, NTH, SMEM_DYN>>>(xh, xm, Wd, bd, out);
}

// round 8
// speedup vs baseline: 1.2120x; 1.2120x over previous
#include <cuda_runtime.h>
#include <cuda_bf16.h>
#include <cstdint>

#define BATCH 2048
#define SEQ   128
#define FEAT  64
#define HID   512
#define NGATE 2048          // 4*HID, gate-interleaved: n = 4*j + g
#define TM    128
#define TN    128           // per warpgroup; CTA covers 2 N-tiles (n0, n0+1024)
#define TK    32
#define NTH   512
#define NCTA  128           // <=148 SMs and smem forces occ=1: barrier liveness guaranteed

// smem stage layout: 6 segments of 10240B (128 rows x 80B; 64B data + 16B pad)
//   seg0 A_hi | seg1 A_mid | seg2 Ba_hi | seg3 Ba_mid | seg4 Bb_hi | seg5 Bb_mid
#define PB       80
#define SEGSZ    10240
#define STAGE    61440
#define BIAS_OFF (2 * STAGE)              // 122880: four 128-float bias tiles
#define SMEM_DYN (BIAS_OFF + 2048)        // 124928

// ---------------- static device buffers ----------------
__device__ __nv_bfloat16 g_U1h[NGATE * HID],  g_U1m[NGATE * HID];
__device__ __nv_bfloat16 g_W1h[NGATE * FEAT], g_W1m[NGATE * FEAT];
__device__ __nv_bfloat16 g_U2h[NGATE * HID],  g_U2m[NGATE * HID];
__device__ __nv_bfloat16 g_W2h[NGATE * HID],  g_W2m[NGATE * HID];
__device__ __nv_bfloat16 g_xh[(size_t)BATCH * SEQ * FEAT], g_xm[(size_t)BATCH * SEQ * FEAT];
__device__ __nv_bfloat16 g_h1h[2][BATCH * HID], g_h1m[2][BATCH * HID];
__device__ __nv_bfloat16 g_h2h[2][BATCH * HID], g_h2m[2][BATCH * HID];
__device__ float g_c1[BATCH * HID], g_c2[BATCH * HID];
__device__ float g_b1i[NGATE], g_b2i[NGATE];
__device__ unsigned g_bar_count = 0;
__device__ unsigned g_bar_gen = 0;

// ---------------- PTX helpers ----------------
__device__ __forceinline__ uint32_t smem_u32(const void* p) {
    uint32_t a;
    asm("{ .reg .u64 t; cvta.to.shared.u64 t, %1; cvt.u32.u64 %0, t; }" : "=r"(a) : "l"(p));
    return a;
}
__device__ __forceinline__ void cpa(uint32_t dst, const void* src) {
    asm volatile("cp.async.cg.shared.global [%0], [%1], 16;" :: "r"(dst), "l"(src));
}
__device__ __forceinline__ void cp_commit() { asm volatile("cp.async.commit_group;"); }
template <int N> __device__ __forceinline__ void cp_wait() {
    asm volatile("cp.async.wait_group %0;" :: "n"(N));
}
__device__ __forceinline__ void ldm4(uint32_t* r, uint32_t addr) {
    asm volatile("ldmatrix.sync.aligned.m8n8.x4.shared.b16 {%0,%1,%2,%3}, [%4];"
        : "=r"(r[0]), "=r"(r[1]), "=r"(r[2]), "=r"(r[3]) : "r"(addr));
}
__device__ __forceinline__ void mma16816(float* c, const uint32_t* a, const uint32_t* b) {
    asm volatile("mma.sync.aligned.m16n8k16.row.col.f32.bf16.bf16.f32 "
        "{%0,%1,%2,%3}, {%4,%5,%6,%7}, {%8,%9}, {%0,%1,%2,%3};"
        : "+f"(c[0]), "+f"(c[1]), "+f"(c[2]), "+f"(c[3])
        : "r"(a[0]), "r"(a[1]), "r"(a[2]), "r"(a[3]), "r"(b[0]), "r"(b[1]));
}
__device__ __forceinline__ float sigmoid_(float v) { return 1.0f / (1.0f + __expf(-v)); }

// grid-wide sense-reversing barrier (128 CTAs, occ=1: residency guaranteed)
__device__ __forceinline__ void grid_barrier() {
    __syncthreads();
    if (threadIdx.x == 0) {
        unsigned my = *(volatile unsigned*)&g_bar_gen;   // sample BEFORE arrive
        __threadfence();
        unsigned prev = atomicAdd(&g_bar_count, 1u);
        if (prev == NCTA - 1) {
            atomicExch(&g_bar_count, 0u);
            __threadfence();
            atomicAdd(&g_bar_gen, 1u);                   // release
        } else {
            while (*(volatile unsigned*)&g_bar_gen == my) __nanosleep(40);
        }
        __threadfence();
    }
    __syncthreads();
}

// ---------------- one fused LSTM step: both N-tiles, shared A staging ----------------
__device__ __forceinline__ void tile_step(
    uint32_t sm_base, int m0, int n0a, int g, int wm, int wn, int lane, int tid,
    const __nv_bfloat16* __restrict__ hph, const __nv_bfloat16* __restrict__ hpm,
    const __nv_bfloat16* __restrict__ Uh,  const __nv_bfloat16* __restrict__ Um, int nRec,
    const __nv_bfloat16* __restrict__ xh,  const __nv_bfloat16* __restrict__ xm, int ldxA,
    const __nv_bfloat16* __restrict__ Wh,  const __nv_bfloat16* __restrict__ Wm, int ldBin, int nIn,
    const float* __restrict__ biasS, float* __restrict__ cst,
    __nv_bfloat16* __restrict__ hoh, __nv_bfloat16* __restrict__ hom, int first)
{
    __syncthreads();   // guard smem stage reuse across consecutive tile_steps

    const int n0b = n0a + (NGATE / 2);

    // per-warp ldmatrix addressing (R4-proven pattern), group g's B segments
    const int rA  = (lane & 7) + ((lane >> 3) & 1) * 8;
    const int kbA = (lane >> 4) * 8;
    const int rB  = (lane & 7) + ((lane >> 4) & 1) * 8;
    const int kbB = ((lane >> 3) & 1) * 8;
    const uint32_t aoff = (uint32_t)(wm * 64 + rA) * PB + kbA * 2;                       // seg0
    const uint32_t boff = (uint32_t)(2 + 2 * g) * SEGSZ + (uint32_t)(wn * 32 + rB) * PB + kbB * 2;

    float acc[4][4][4];
    #pragma unroll
    for (int a = 0; a < 4; ++a)
        #pragma unroll
        for (int b = 0; b < 4; ++b)
            #pragma unroll
            for (int c = 0; c < 4; ++c) acc[a][b][c] = 0.0f;

    const int nb = nRec + nIn;

    auto stage_load = [&](int it, int s) {
        const __nv_bfloat16 *Ah, *Am, *Bh, *Bm; int lda, ldb, k0;
        if (it < nRec) { Ah = hph; Am = hpm; lda = HID;  Bh = Uh; Bm = Um; ldb = HID;   k0 = it * TK; }
        else           { Ah = xh;  Am = xm;  lda = ldxA; Bh = Wh; Bm = Wm; ldb = ldBin; k0 = (it - nRec) * TK; }
        const uint32_t sb = sm_base + (uint32_t)s * STAGE;
        #pragma unroll
        for (int i = 0; i < 6; ++i) {                  // 3072 16B tasks / 512 threads
            int e = tid + i * NTH;
            int seg = e >> 9;
            int r = (e >> 2) & 127, c = e & 3;
            uint32_t d = sb + (uint32_t)seg * SEGSZ + (uint32_t)r * PB + c * 16;
            const __nv_bfloat16* src;
            if (seg == 0)      src = Ah + (size_t)(m0 + r) * lda + k0 + c * 8;
            else if (seg == 1) src = Am + (size_t)(m0 + r) * lda + k0 + c * 8;
            else if (seg == 2) src = Bh + (size_t)(n0a + r) * ldb + k0 + c * 8;
            else if (seg == 3) src = Bm + (size_t)(n0a + r) * ldb + k0 + c * 8;
            else if (seg == 4) src = Bh + (size_t)(n0b + r) * ldb + k0 + c * 8;
            else               src = Bm + (size_t)(n0b + r) * ldb + k0 + c * 8;
            cpa(d, src);
        }
    };

    stage_load(0, 0);
    cp_commit();

    for (int it = 0; it < nb; ++it) {
        if (it + 1 < nb) {
            stage_load(it + 1, (it + 1) & 1);
            cp_commit();
            cp_wait<1>();
        } else {
            cp_wait<0>();
        }
        __syncthreads();

        const uint32_t sb = sm_base + (uint32_t)(it & 1) * STAGE;
        #pragma unroll
        for (int ks = 0; ks < 2; ++ks) {
            uint32_t bh[2][4], bm[2][4];
            #pragma unroll
            for (int p = 0; p < 2; ++p) {
                uint32_t ba = sb + boff + (uint32_t)p * (16 * PB) + ks * 32;
                ldm4(bh[p], ba);
                ldm4(bm[p], ba + SEGSZ);
            }
            #pragma unroll
            for (int mi = 0; mi < 4; ++mi) {
                uint32_t ah[4], am[4];
                uint32_t aa = sb + aoff + (uint32_t)mi * (16 * PB) + ks * 32;
                ldm4(ah, aa);
                ldm4(am, aa + SEGSZ);
                #pragma unroll
                for (int ni = 0; ni < 4; ++ni) {
                    const uint32_t* bhp = &bh[ni >> 1][(ni & 1) * 2];
                    const uint32_t* bmp = &bm[ni >> 1][(ni & 1) * 2];
                    mma16816(acc[mi][ni], ah, bhp);
                    mma16816(acc[mi][ni], am, bhp);
                    mma16816(acc[mi][ni], ah, bmp);
                }
            }
        }
        __syncthreads();
    }

    // epilogue: bias + gate exchange + fused cell  (group g owns hidden units jbase..)
    const int jbase = ((n0a + g * (NGATE / 2)) >> 2) + wn * 8;
    #pragma unroll
    for (int mi = 0; mi < 4; ++mi) {
        #pragma unroll
        for (int ni = 0; ni < 4; ++ni) {
            const int nl = wn * 32 + ni * 8 + (lane & 3) * 2;
            const float bb0 = biasS[nl], bb1 = biasS[nl + 1];
            #pragma unroll
            for (int r = 0; r < 2; ++r) {
                float v0 = acc[mi][ni][r * 2 + 0] + bb0;
                float v1 = acc[mi][ni][r * 2 + 1] + bb1;
                float o0 = __shfl_xor_sync(0xffffffffu, v0, 1);
                float o1 = __shfl_xor_sync(0xffffffffu, v1, 1);
                if ((lane & 1) == 0) {
                    const int m = m0 + wm * 64 + mi * 16 + (lane >> 2) + r * 8;
                    const int j = jbase + ni * 2 + ((lane & 3) >> 1);
                    const size_t idx = (size_t)m * HID + j;
                    float cp = first ? 0.0f : cst[idx];
                    float iv = sigmoid_(v0), fv = sigmoid_(v1);
                    float ci = fmaxf(o0, 0.0f), ov = sigmoid_(o1);
                    float cn = fv * cp + iv * ci;
                    cst[idx] = cn;
                    float hv = ov * fmaxf(cn, 0.0f);
                    __nv_bfloat16 hh = __float2bfloat16(hv);
                    hoh[idx] = hh;
                    hom[idx] = __float2bfloat16(hv - __bfloat162float(hh));
                }
            }
        }
    }
}

// ---------------- persistent kernel: all 128 steps, both layers, dense head ----------------
__global__ __launch_bounds__(NTH, 1) void lstm_persistent(
    const __nv_bfloat16* __restrict__ xh, const __nv_bfloat16* __restrict__ xm,
    const float* __restrict__ Wd, const float* __restrict__ bd, float* __restrict__ out)
{
    extern __shared__ char smem[];
    const uint32_t sm_base = smem_u32(smem);
    float* biasS = reinterpret_cast<float*>(smem + BIAS_OFF);   // [4][128]: L1a,L1b,L2a,L2b

    const int tid  = threadIdx.x;
    const int wid  = tid >> 5;
    const int lane = tid & 31;
    const int g    = wid >> 3;          // warpgroup 0/1 -> N-tile a/b
    const int w8   = wid & 7;
    const int wm   = w8 >> 2;
    const int wn   = w8 & 3;
    const int bid  = blockIdx.x;
    const int m0   = (bid & 15) * TM;
    const int n0a  = (bid >> 4) * TN;   // 0..7 * 128; group1 adds 1024

    if (tid < TN) {
        biasS[0 * TN + tid] = g_b1i[n0a + tid];
        biasS[1 * TN + tid] = g_b1i[n0a + (NGATE / 2) + tid];
        biasS[2 * TN + tid] = g_b2i[n0a + tid];
        biasS[3 * TN + tid] = g_b2i[n0a + (NGATE / 2) + tid];
    }
    __syncthreads();

    __nv_bfloat16* h1h[2] = {g_h1h[0], g_h1h[1]};
    __nv_bfloat16* h1m[2] = {g_h1m[0], g_h1m[1]};
    __nv_bfloat16* h2h[2] = {g_h2h[0], g_h2h[1]};
    __nv_bfloat16* h2m[2] = {g_h2m[0], g_h2m[1]};

    // phase p: L1(t=p) and L2(t=p-1); both depend only on pre-barrier data
    for (int p = 0; p <= SEQ; ++p) {
        if (p < SEQ) {
            const int t = p, cu = t & 1, pv = (t - 1) & 1;
            tile_step(sm_base, m0, n0a, g, wm, wn, lane, tid,
                      t ? h1h[pv] : nullptr, t ? h1m[pv] : nullptr,
                      g_U1h, g_U1m, t ? (HID / TK) : 0,
                      xh + (size_t)t * FEAT, xm + (size_t)t * FEAT, SEQ * FEAT,
                      g_W1h, g_W1m, FEAT, FEAT / TK,
                      biasS + g * TN, g_c1, h1h[cu], h1m[cu], t == 0);
        }
        if (p >= 1) {
            const int t = p - 1, cu = t & 1, pv = (t - 1) & 1;
            tile_step(sm_base, m0, n0a, g, wm, wn, lane, tid,
                      t ? h2h[pv] : nullptr, t ? h2m[pv] : nullptr,
                      g_U2h, g_U2m, t ? (HID / TK) : 0,
                      h1h[cu], h1m[cu], HID,
                      g_W2h, g_W2m, HID, HID / TK,
                      biasS + (2 + g) * TN, g_c2, h2h[cu], h2m[cu], t == 0);
        }
        grid_barrier();
    }

    // dense head: 128 CTAs x 16 warps = 2048 batch rows
    {
        const int fin = (SEQ - 1) & 1;
        const int b = bid * 16 + wid;
        const __nv_bfloat16* rh = h2h[fin] + (size_t)b * HID;
        const __nv_bfloat16* rm = h2m[fin] + (size_t)b * HID;
        float s = 0.0f;
        #pragma unroll
        for (int k = lane; k < HID; k += 32)
            s += (__bfloat162float(rh[k]) + __bfloat162float(rm[k])) * Wd[k];
        #pragma unroll
        for (int o = 16; o > 0; o >>= 1) s += __shfl_xor_sync(0xffffffffu, s, o);
        if (lane == 0) out[b] = s + bd[0];
    }
}

// ---------------- prep kernels ----------------
__global__ void prep_weights_all(const float* __restrict__ U1, const float* __restrict__ W1,
                                 const float* __restrict__ U2, const float* __restrict__ W2)
{
    const int NU = NGATE * HID, NW = NGATE * FEAT;
    int idx = blockIdx.x * blockDim.x + threadIdx.x;
    const float* src; __nv_bfloat16 *dh, *dm; int K, li;
    if (idx < NU)               { src = U1; dh = g_U1h; dm = g_U1m; K = HID;  li = idx; }
    else if (idx < NU + NW)     { src = W1; dh = g_W1h; dm = g_W1m; K = FEAT; li = idx - NU; }
    else if (idx < 2 * NU + NW) { src = U2; dh = g_U2h; dm = g_U2m; K = HID;  li = idx - NU - NW; }
    else if (idx < 3 * NU + NW) { src = W2; dh = g_W2h; dm = g_W2m; K = HID;  li = idx - 2 * NU - NW; }
    else return;
    int n = li / K, k = li - n * K;
    int col = (n & 3) * HID + (n >> 2);          // gate-interleave: n = 4j+g
    float v = src[(size_t)k * NGATE + col];
    __nv_bfloat16 h = __float2bfloat16(v);
    dh[li] = h;
    dm[li] = __float2bfloat16(v - __bfloat162float(h));
}

__global__ void prep_bias(const float* __restrict__ b1, const float* __restrict__ b2)
{
    int n = blockIdx.x * blockDim.x + threadIdx.x;
    if (n >= NGATE) return;
    int col = (n & 3) * HID + (n >> 2);
    g_b1i[n] = b1[col];
    g_b2i[n] = b2[col];
}

__global__ void prep_x(const float* __restrict__ x, int n)
{
    int i = blockIdx.x * blockDim.x + threadIdx.x;
    if (i >= n) return;
    float v = x[i];
    __nv_bfloat16 h = __float2bfloat16(v);
    g_xh[i] = h;
    g_xm[i] = __float2bfloat16(v - __bfloat162float(h));
}

extern "C" void kernel_launch(void* const* d_in, const int* in_sizes, int n_in,
                              void* d_out, int out_size)
{
    const float* x  = (const float*)d_in[0];
    const float* W1 = (const float*)d_in[1];
    const float* U1 = (const float*)d_in[2];
    const float* b1 = (const float*)d_in[3];
    const float* W2 = (const float*)d_in[4];
    const float* U2 = (const float*)d_in[5];
    const float* b2 = (const float*)d_in[6];
    const float* Wd = (const float*)d_in[7];
    const float* bd = (const float*)d_in[8];
    float* out = (float*)d_out;

    cudaFuncSetAttribute(lstm_persistent, cudaFuncAttributeMaxDynamicSharedMemorySize, SMEM_DYN);

    __nv_bfloat16* xh; __nv_bfloat16* xm;
    cudaGetSymbolAddress((void**)&xh, g_xh);
    cudaGetSymbolAddress((void**)&xm, g_xm);

    {
        int ntot = 3 * NGATE * HID + NGATE * FEAT;
        prep_weights_all<<<(ntot + 255) / 256, 256>>>(U1, W1, U2, W2);
        prep_bias<<<(NGATE + 255) / 256, 256>>>(b1, b2);
        int nx = BATCH * SEQ * FEAT;
        prep_x<<<(nx + 255) / 256, 256>>>(x, nx);
    }

    lstm_persistent<<<NCTA, NTH, SMEM_DYN>>>(xh, xm, Wd, bd, out);
}

// round 9
// speedup vs baseline: 1.2203x; 1.0069x over previous
#include <cuda_runtime.h>
#include <cuda_bf16.h>
#include <cstdint>

#define BATCH 2048
#define SEQ   128
#define FEAT  64
#define HID   512
#define NGATE 2048          // 4*HID, gate-interleaved: n = 4*j + g
#define TM    128
#define TN    128           // per warpgroup; CTA covers 2 N-tiles (n0, n0+1024)
#define TK    32
#define NTH   512
#define NCTA  128           // <=148 SMs and smem forces occ=1: barrier liveness guaranteed

// smem stage layout: 6 segments of 10240B (128 rows x 80B; 64B data + 16B pad)
//   seg0 A_hi | seg1 A_mid | seg2 Ba_hi | seg3 Ba_mid | seg4 Bb_hi | seg5 Bb_mid
#define PB       80
#define SEGSZ    10240
#define STAGE    61440
#define BIAS_OFF (2 * STAGE)              // 122880: four 128-float bias tiles
#define SMEM_DYN (BIAS_OFF + 2048)        // 124928

// ---------------- static device buffers ----------------
__device__ __nv_bfloat16 g_U1h[NGATE * HID],  g_U1m[NGATE * HID];
__device__ __nv_bfloat16 g_W1h[NGATE * FEAT], g_W1m[NGATE * FEAT];
__device__ __nv_bfloat16 g_U2h[NGATE * HID],  g_U2m[NGATE * HID];
__device__ __nv_bfloat16 g_W2h[NGATE * HID],  g_W2m[NGATE * HID];
__device__ __nv_bfloat16 g_xh[(size_t)BATCH * SEQ * FEAT], g_xm[(size_t)BATCH * SEQ * FEAT];
__device__ __nv_bfloat16 g_h1h[2][BATCH * HID], g_h1m[2][BATCH * HID];
__device__ __nv_bfloat16 g_h2h[2][BATCH * HID], g_h2m[2][BATCH * HID];
__device__ float g_c1[BATCH * HID], g_c2[BATCH * HID];
__device__ float g_b1i[NGATE], g_b2i[NGATE];
__device__ unsigned g_bar_count = 0;
__device__ unsigned g_bar_gen = 0;

// ---------------- PTX helpers ----------------
__device__ __forceinline__ uint32_t smem_u32(const void* p) {
    uint32_t a;
    asm("{ .reg .u64 t; cvta.to.shared.u64 t, %1; cvt.u32.u64 %0, t; }" : "=r"(a) : "l"(p));
    return a;
}
__device__ __forceinline__ void cpa(uint32_t dst, const void* src) {
    asm volatile("cp.async.cg.shared.global [%0], [%1], 16;" :: "r"(dst), "l"(src));
}
__device__ __forceinline__ void cp_commit() { asm volatile("cp.async.commit_group;"); }
template <int N> __device__ __forceinline__ void cp_wait() {
    asm volatile("cp.async.wait_group %0;" :: "n"(N));
}
__device__ __forceinline__ void ldm4(uint32_t* r, uint32_t addr) {
    asm volatile("ldmatrix.sync.aligned.m8n8.x4.shared.b16 {%0,%1,%2,%3}, [%4];"
        : "=r"(r[0]), "=r"(r[1]), "=r"(r[2]), "=r"(r[3]) : "r"(addr));
}
__device__ __forceinline__ void mma16816(float* c, const uint32_t* a, const uint32_t* b) {
    asm volatile("mma.sync.aligned.m16n8k16.row.col.f32.bf16.bf16.f32 "
        "{%0,%1,%2,%3}, {%4,%5,%6,%7}, {%8,%9}, {%0,%1,%2,%3};"
        : "+f"(c[0]), "+f"(c[1]), "+f"(c[2]), "+f"(c[3])
        : "r"(a[0]), "r"(a[1]), "r"(a[2]), "r"(a[3]), "r"(b[0]), "r"(b[1]));
}
__device__ __forceinline__ float sigmoid_(float v) { return 1.0f / (1.0f + __expf(-v)); }

// grid-wide sense-reversing barrier (128 CTAs, occ=1: residency guaranteed)
__device__ __forceinline__ void grid_barrier() {
    __syncthreads();
    if (threadIdx.x == 0) {
        unsigned my = *(volatile unsigned*)&g_bar_gen;   // sample BEFORE arrive
        __threadfence();
        unsigned prev = atomicAdd(&g_bar_count, 1u);
        if (prev == NCTA - 1) {
            atomicExch(&g_bar_count, 0u);
            __threadfence();
            atomicAdd(&g_bar_gen, 1u);                   // release
        } else {
            while (*(volatile unsigned*)&g_bar_gen == my) __nanosleep(40);
        }
        __threadfence();
    }
    __syncthreads();
}

// ---------------- one fused LSTM step: both N-tiles, shared A staging ----------------
__device__ __forceinline__ void tile_step(
    uint32_t sm_base, int m0, int n0a, int g, int wm, int wn, int lane, int tid,
    const __nv_bfloat16* __restrict__ hph, const __nv_bfloat16* __restrict__ hpm,
    const __nv_bfloat16* __restrict__ Uh,  const __nv_bfloat16* __restrict__ Um, int nRec,
    const __nv_bfloat16* __restrict__ xh,  const __nv_bfloat16* __restrict__ xm, int ldxA,
    const __nv_bfloat16* __restrict__ Wh,  const __nv_bfloat16* __restrict__ Wm, int ldBin, int nIn,
    const float* __restrict__ biasS, float* __restrict__ cst,
    __nv_bfloat16* __restrict__ hoh, __nv_bfloat16* __restrict__ hom, int first)
{
    __syncthreads();   // guard smem stage reuse across consecutive tile_steps

    const int n0b = n0a + (NGATE / 2);

    // per-warp ldmatrix addressing, group g's B segments
    const int rA  = (lane & 7) + ((lane >> 3) & 1) * 8;
    const int kbA = (lane >> 4) * 8;
    const int rB  = (lane & 7) + ((lane >> 4) & 1) * 8;
    const int kbB = ((lane >> 3) & 1) * 8;
    const uint32_t aoff = (uint32_t)(wm * 64 + rA) * PB + kbA * 2;                       // seg0
    const uint32_t boff = (uint32_t)(2 + 2 * g) * SEGSZ + (uint32_t)(wn * 32 + rB) * PB + kbB * 2;

    float acc[4][4][4];
    #pragma unroll
    for (int a = 0; a < 4; ++a)
        #pragma unroll
        for (int b = 0; b < 4; ++b)
            #pragma unroll
            for (int c = 0; c < 4; ++c) acc[a][b][c] = 0.0f;

    const int nb = nRec + nIn;

    auto stage_load = [&](int it, int s) {
        const __nv_bfloat16 *Ah, *Am, *Bh, *Bm; int lda, ldb, k0;
        if (it < nRec) { Ah = hph; Am = hpm; lda = HID;  Bh = Uh; Bm = Um; ldb = HID;   k0 = it * TK; }
        else           { Ah = xh;  Am = xm;  lda = ldxA; Bh = Wh; Bm = Wm; ldb = ldBin; k0 = (it - nRec) * TK; }
        const uint32_t sb = sm_base + (uint32_t)s * STAGE;
        #pragma unroll
        for (int i = 0; i < 6; ++i) {                  // 3072 16B tasks / 512 threads
            int e = tid + i * NTH;
            int seg = e >> 9;
            int r = (e >> 2) & 127, c = e & 3;
            uint32_t d = sb + (uint32_t)seg * SEGSZ + (uint32_t)r * PB + c * 16;
            const __nv_bfloat16* src;
            if (seg == 0)      src = Ah + (size_t)(m0 + r) * lda + k0 + c * 8;
            else if (seg == 1) src = Am + (size_t)(m0 + r) * lda + k0 + c * 8;
            else if (seg == 2) src = Bh + (size_t)(n0a + r) * ldb + k0 + c * 8;
            else if (seg == 3) src = Bm + (size_t)(n0a + r) * ldb + k0 + c * 8;
            else if (seg == 4) src = Bh + (size_t)(n0b + r) * ldb + k0 + c * 8;
            else               src = Bm + (size_t)(n0b + r) * ldb + k0 + c * 8;
            cpa(d, src);
        }
    };

    stage_load(0, 0);
    cp_commit();

    for (int it = 0; it < nb; ++it) {
        if (it + 1 < nb) {
            stage_load(it + 1, (it + 1) & 1);
            cp_commit();
            cp_wait<1>();
        } else {
            cp_wait<0>();
        }
        __syncthreads();

        const uint32_t sb = sm_base + (uint32_t)(it & 1) * STAGE;
        #pragma unroll
        for (int ks = 0; ks < 2; ++ks) {
            uint32_t bh[2][4], bm[2][4];
            #pragma unroll
            for (int p = 0; p < 2; ++p) {
                uint32_t ba = sb + boff + (uint32_t)p * (16 * PB) + ks * 32;
                ldm4(bh[p], ba);
                ldm4(bm[p], ba + SEGSZ);
            }
            // process mi tiles in pairs; MMAs issued TERM-MAJOR:
            // 8 independent MMAs per term group -> dependent acc reuses spaced 8 apart
            #pragma unroll
            for (int mp = 0; mp < 2; ++mp) {
                uint32_t ah[2][4], am[2][4];
                #pragma unroll
                for (int q = 0; q < 2; ++q) {
                    uint32_t aa = sb + aoff + (uint32_t)(mp * 2 + q) * (16 * PB) + ks * 32;
                    ldm4(ah[q], aa);
                    ldm4(am[q], aa + SEGSZ);
                }
                // term 1: ah * bh  (8 independent)
                #pragma unroll
                for (int q = 0; q < 2; ++q)
                    #pragma unroll
                    for (int ni = 0; ni < 4; ++ni)
                        mma16816(acc[mp * 2 + q][ni], ah[q], &bh[ni >> 1][(ni & 1) * 2]);
                // term 2: am * bh  (8 independent)
                #pragma unroll
                for (int q = 0; q < 2; ++q)
                    #pragma unroll
                    for (int ni = 0; ni < 4; ++ni)
                        mma16816(acc[mp * 2 + q][ni], am[q], &bh[ni >> 1][(ni & 1) * 2]);
                // term 3: ah * bm  (8 independent)
                #pragma unroll
                for (int q = 0; q < 2; ++q)
                    #pragma unroll
                    for (int ni = 0; ni < 4; ++ni)
                        mma16816(acc[mp * 2 + q][ni], ah[q], &bm[ni >> 1][(ni & 1) * 2]);
            }
        }
        __syncthreads();
    }

    // epilogue: bias + gate exchange + fused cell  (group g owns hidden units jbase..)
    const int jbase = ((n0a + g * (NGATE / 2)) >> 2) + wn * 8;
    #pragma unroll
    for (int mi = 0; mi < 4; ++mi) {
        #pragma unroll
        for (int ni = 0; ni < 4; ++ni) {
            const int nl = wn * 32 + ni * 8 + (lane & 3) * 2;
            const float bb0 = biasS[nl], bb1 = biasS[nl + 1];
            #pragma unroll
            for (int r = 0; r < 2; ++r) {
                float v0 = acc[mi][ni][r * 2 + 0] + bb0;
                float v1 = acc[mi][ni][r * 2 + 1] + bb1;
                float o0 = __shfl_xor_sync(0xffffffffu, v0, 1);
                float o1 = __shfl_xor_sync(0xffffffffu, v1, 1);
                if ((lane & 1) == 0) {
                    const int m = m0 + wm * 64 + mi * 16 + (lane >> 2) + r * 8;
                    const int j = jbase + ni * 2 + ((lane & 3) >> 1);
                    const size_t idx = (size_t)m * HID + j;
                    float cp = first ? 0.0f : cst[idx];
                    float iv = sigmoid_(v0), fv = sigmoid_(v1);
                    float ci = fmaxf(o0, 0.0f), ov = sigmoid_(o1);
                    float cn = fv * cp + iv * ci;
                    cst[idx] = cn;
                    float hv = ov * fmaxf(cn, 0.0f);
                    __nv_bfloat16 hh = __float2bfloat16(hv);
                    hoh[idx] = hh;
                    hom[idx] = __float2bfloat16(hv - __bfloat162float(hh));
                }
            }
        }
    }
}

// ---------------- persistent kernel: all 128 steps, both layers, dense head ----------------
__global__ __launch_bounds__(NTH, 1) void lstm_persistent(
    const __nv_bfloat16* __restrict__ xh, const __nv_bfloat16* __restrict__ xm,
    const float* __restrict__ Wd, const float* __restrict__ bd, float* __restrict__ out)
{
    extern __shared__ char smem[];
    const uint32_t sm_base = smem_u32(smem);
    float* biasS = reinterpret_cast<float*>(smem + BIAS_OFF);   // [4][128]: L1a,L1b,L2a,L2b

    const int tid  = threadIdx.x;
    const int wid  = tid >> 5;
    const int lane = tid & 31;
    const int g    = wid >> 3;          // warpgroup 0/1 -> N-tile a/b
    const int w8   = wid & 7;
    const int wm   = w8 >> 2;
    const int wn   = w8 & 3;
    const int bid  = blockIdx.x;
    const int m0   = (bid & 15) * TM;
    const int n0a  = (bid >> 4) * TN;   // 0..7 * 128; group1 adds 1024

    if (tid < TN) {
        biasS[0 * TN + tid] = g_b1i[n0a + tid];
        biasS[1 * TN + tid] = g_b1i[n0a + (NGATE / 2) + tid];
        biasS[2 * TN + tid] = g_b2i[n0a + tid];
        biasS[3 * TN + tid] = g_b2i[n0a + (NGATE / 2) + tid];
    }
    __syncthreads();

    __nv_bfloat16* h1h[2] = {g_h1h[0], g_h1h[1]};
    __nv_bfloat16* h1m[2] = {g_h1m[0], g_h1m[1]};
    __nv_bfloat16* h2h[2] = {g_h2h[0], g_h2h[1]};
    __nv_bfloat16* h2m[2] = {g_h2m[0], g_h2m[1]};

    // phase p: L1(t=p) and L2(t=p-1); both depend only on pre-barrier data
    for (int p = 0; p <= SEQ; ++p) {
        if (p < SEQ) {
            const int t = p, cu = t & 1, pv = (t - 1) & 1;
            tile_step(sm_base, m0, n0a, g, wm, wn, lane, tid,
                      t ? h1h[pv] : nullptr, t ? h1m[pv] : nullptr,
                      g_U1h, g_U1m, t ? (HID / TK) : 0,
                      xh + (size_t)t * FEAT, xm + (size_t)t * FEAT, SEQ * FEAT,
                      g_W1h, g_W1m, FEAT, FEAT / TK,
                      biasS + g * TN, g_c1, h1h[cu], h1m[cu], t == 0);
        }
        if (p >= 1) {
            const int t = p - 1, cu = t & 1, pv = (t - 1) & 1;
            tile_step(sm_base, m0, n0a, g, wm, wn, lane, tid,
                      t ? h2h[pv] : nullptr, t ? h2m[pv] : nullptr,
                      g_U2h, g_U2m, t ? (HID / TK) : 0,
                      h1h[cu], h1m[cu], HID,
                      g_W2h, g_W2m, HID, HID / TK,
                      biasS + (2 + g) * TN, g_c2, h2h[cu], h2m[cu], t == 0);
        }
        grid_barrier();
    }

    // dense head: 128 CTAs x 16 warps = 2048 batch rows
    {
        const int fin = (SEQ - 1) & 1;
        const int b = bid * 16 + wid;
        const __nv_bfloat16* rh = h2h[fin] + (size_t)b * HID;
        const __nv_bfloat16* rm = h2m[fin] + (size_t)b * HID;
        float s = 0.0f;
        #pragma unroll
        for (int k = lane; k < HID; k += 32)
            s += (__bfloat162float(rh[k]) + __bfloat162float(rm[k])) * Wd[k];
        #pragma unroll
        for (int o = 16; o > 0; o >>= 1) s += __shfl_xor_sync(0xffffffffu, s, o);
        if (lane == 0) out[b] = s + bd[0];
    }
}

// ---------------- prep kernels ----------------
__global__ void prep_weights_all(const float* __restrict__ U1, const float* __restrict__ W1,
                                 const float* __restrict__ U2, const float* __restrict__ W2)
{
    const int NU = NGATE * HID, NW = NGATE * FEAT;
    int idx = blockIdx.x * blockDim.x + threadIdx.x;
    const float* src; __nv_bfloat16 *dh, *dm; int K, li;
    if (idx < NU)               { src = U1; dh = g_U1h; dm = g_U1m; K = HID;  li = idx; }
    else if (idx < NU + NW)     { src = W1; dh = g_W1h; dm = g_W1m; K = FEAT; li = idx - NU; }
    else if (idx < 2 * NU + NW) { src = U2; dh = g_U2h; dm = g_U2m; K = HID;  li = idx - NU - NW; }
    else if (idx < 3 * NU + NW) { src = W2; dh = g_W2h; dm = g_W2m; K = HID;  li = idx - 2 * NU - NW; }
    else return;
    int n = li / K, k = li - n * K;
    int col = (n & 3) * HID + (n >> 2);          // gate-interleave: n = 4j+g
    float v = src[(size_t)k * NGATE + col];
    __nv_bfloat16 h = __float2bfloat16(v);
    dh[li] = h;
    dm[li] = __float2bfloat16(v - __bfloat162float(h));
}

__global__ void prep_bias(const float* __restrict__ b1, const float* __restrict__ b2)
{
    int n = blockIdx.x * blockDim.x + threadIdx.x;
    if (n >= NGATE) return;
    int col = (n & 3) * HID + (n >> 2);
    g_b1i[n] = b1[col];
    g_b2i[n] = b2[col];
}

__global__ void prep_x(const float* __restrict__ x, int n)
{
    int i = blockIdx.x * blockDim.x + threadIdx.x;
    if (i >= n) return;
    float v = x[i];
    __nv_bfloat16 h = __float2bfloat16(v);
    g_xh[i] = h;
    g_xm[i] = __float2bfloat16(v - __bfloat162float(h));
}

extern "C" void kernel_launch(void* const* d_in, const int* in_sizes, int n_in,
                              void* d_out, int out_size)
{
    const float* x  = (const float*)d_in[0];
    const float* W1 = (const float*)d_in[1];
    const float* U1 = (const float*)d_in[2];
    const float* b1 = (const float*)d_in[3];
    const float* W2 = (const float*)d_in[4];
    const float* U2 = (const float*)d_in[5];
    const float* b2 = (const float*)d_in[6];
    const float* Wd = (const float*)d_in[7];
    const float* bd = (const float*)d_in[8];
    float* out = (float*)d_out;

    cudaFuncSetAttribute(lstm_persistent, cudaFuncAttributeMaxDynamicSharedMemorySize, SMEM_DYN);

    __nv_bfloat16* xh; __nv_bfloat16* xm;
    cudaGetSymbolAddress((void**)&xh, g_xh);
    cudaGetSymbolAddress((void**)&xm, g_xm);

    {
        int ntot = 3 * NGATE * HID + NGATE * FEAT;
        prep_weights_all<<<(ntot + 255) / 256, 256>>>(U1, W1, U2, W2);
        prep_bias<<<(NGATE + 255) / 256, 256>>>(b1, b2);
        int nx = BATCH * SEQ * FEAT;
        prep_x<<<(nx + 255) / 256, 256>>>(x, nx);
    }

    lstm_persistent<<<NCTA, NTH, SMEM_DYN>>>(xh, xm, Wd, bd, out);
}